// round 15
// baseline (speedup 1.0000x reference)
#include <cuda_runtime.h>
#include <cuda_fp16.h>
#include <math.h>

#define IN_CH 128
#define HID 64
#define NMAX 50000
#define EMAX 800000

// Scratch (__device__ globals; no allocation allowed)
__device__ float   g_deg[NMAX];               // degree (raw; consumers rsqrt)
__device__ __half2 g_h16[NMAX * (HID / 2)];   // h' fp16 (gather source, both layers)
__device__ __half2 g_agg1[NMAX * (HID / 2)];  // layer-1 aggregation (fp16 REDs)
__device__ __half2 g_agg2[NMAX * (HID / 2)];  // layer-2 aggregation (fp16 REDs)

// pack two fp32 into one 32-bit half2 payload
static __device__ __forceinline__ unsigned pack_h2(float a, float b) {
    __half2 h = __floats2half2_rn(a, b);
    return *(unsigned*)&h;
}

// ---------------------------------------------------------------------------
__global__ void init_deg_kernel(int n) {
    int i = blockIdx.x * blockDim.x + threadIdx.x;
    if (i < n) g_deg[i] = 1.0f;               // self-loop contributes 1
}

__global__ void degree_kernel(const int* __restrict__ dst, int e) {
    int i = blockIdx.x * blockDim.x + threadIdx.x;
    if (i < e) {
        float* p = &g_deg[__ldg(dst + i)];
        asm volatile("red.global.add.f32 [%0], %1;" :: "l"(p), "f"(1.0f) : "memory");
    }
}

// ---------------------------------------------------------------------------
// GEMM: out[i][c] = dinv[i] * sum_k in[i][k] * W[k][c],  dinv = rsqrt(deg) inline.
// Dual-store fp16: -> H16 (edge gather source) and -> AGG16 (self-loop init).
// TRANS: input read from fp16 AGG of previous layer, z = relu(dinv*agg + bIn).
// 128 threads -> 64 nodes x 64 cols (grid 782 -> ~5.3 CTAs/SM, latency hidden).
// Thread (tx,ty): cols {4tx..+4, 4tx+32..+4}, nodes 4*ty..+4.
// Per warp-k: 3 LDS.128 feed 16 FFMA2 -> fma-side of the crossbar balance.
template <int K, bool TRANS>
__global__ void __launch_bounds__(128, 5)
gemm_kernel(const float* __restrict__ X, const __half2* __restrict__ X16,
            const float* __restrict__ W, const float* __restrict__ bIn,
            __half2* __restrict__ H16, __half2* __restrict__ AGG16, int n) {
    constexpr int KC = 64;
    constexpr int NC = K / KC;
    __shared__ float Ws[KC * HID];            // 16KB [k][col]
    __shared__ float Xs[KC * 64];             // 16KB [k][node] (transposed)
    const int t = threadIdx.x;
    const int node0 = blockIdx.x * 64;

    const int tx = t & 7;
    const int ty = t >> 3;                    // 0..15
    const int cA = tx * 4;
    const int n0 = ty * 4;                    // 4 nodes per thread

    unsigned long long acc[4][4];             // [node j][col pair] f32x2
#pragma unroll
    for (int j = 0; j < 4; ++j)
#pragma unroll
        for (int p = 0; p < 4; ++p) acc[j][p] = 0ULL;

#pragma unroll
    for (int c = 0; c < NC; ++c) {
        const int k0 = c * KC;
        if (c) __syncthreads();

        // W chunk: 4096 floats / 128 threads = 8 float4 each, coalesced
#pragma unroll
        for (int i = 0; i < KC * HID / 512; ++i)
            *(float4*)(Ws + i * 512 + t * 4) =
                *(const float4*)(W + k0 * HID + i * 512 + t * 4);

        // X chunk: thread t<64 streams row node0+t, transposes into Xs[k][t]
        if (t < 64) {
            const int mynode = node0 + t;
            const bool ok = mynode < n;
            const float mydi = (TRANS && ok) ? rsqrtf(g_deg[mynode]) : 0.f;
#pragma unroll
            for (int g = 0; g < KC / 4; ++g) {
                float4 v = make_float4(0.f, 0.f, 0.f, 0.f);
                if (ok) {
                    if (TRANS) {
                        uint2 r = *(const uint2*)(X16 + mynode * (HID / 2) + (k0 + g * 4) / 2);
                        float2 f0 = __half22float2(*(__half2*)&r.x);
                        float2 f1 = __half22float2(*(__half2*)&r.y);
                        float4 bb = *(const float4*)(bIn + k0 + g * 4);
                        v.x = fmaxf(fmaf(mydi, f0.x, bb.x), 0.f);
                        v.y = fmaxf(fmaf(mydi, f0.y, bb.y), 0.f);
                        v.z = fmaxf(fmaf(mydi, f1.x, bb.z), 0.f);
                        v.w = fmaxf(fmaf(mydi, f1.y, bb.w), 0.f);
                    } else {
                        v = *(const float4*)(X + mynode * K + k0 + g * 4);
                    }
                }
                Xs[(g * 4 + 0) * 64 + t] = v.x;
                Xs[(g * 4 + 1) * 64 + t] = v.y;
                Xs[(g * 4 + 2) * 64 + t] = v.z;
                Xs[(g * 4 + 3) * 64 + t] = v.w;
            }
        }
        __syncthreads();

#pragma unroll 4
        for (int k = 0; k < KC; ++k) {
            ulonglong2 wA = *(const ulonglong2*)(Ws + k * HID + cA);
            ulonglong2 wB = *(const ulonglong2*)(Ws + k * HID + cA + 32);
            float4 xa = *(const float4*)(Xs + k * 64 + n0);
            float xs[4] = {xa.x, xa.y, xa.z, xa.w};
#pragma unroll
            for (int j = 0; j < 4; ++j) {
                unsigned long long xx;
                asm("mov.b64 %0, {%1, %1};" : "=l"(xx) : "f"(xs[j]));
                asm("fma.rn.f32x2 %0, %1, %2, %0;" : "+l"(acc[j][0]) : "l"(wA.x), "l"(xx));
                asm("fma.rn.f32x2 %0, %1, %2, %0;" : "+l"(acc[j][1]) : "l"(wA.y), "l"(xx));
                asm("fma.rn.f32x2 %0, %1, %2, %0;" : "+l"(acc[j][2]) : "l"(wB.x), "l"(xx));
                asm("fma.rn.f32x2 %0, %1, %2, %0;" : "+l"(acc[j][3]) : "l"(wB.y), "l"(xx));
            }
        }
    }

#pragma unroll
    for (int j = 0; j < 4; ++j) {
        int node = node0 + n0 + j;
        if (node < n) {
            float di = rsqrtf(g_deg[node]);
            float o[8];
            asm("mov.b64 {%0,%1}, %2;" : "=f"(o[0]), "=f"(o[1]) : "l"(acc[j][0]));
            asm("mov.b64 {%0,%1}, %2;" : "=f"(o[2]), "=f"(o[3]) : "l"(acc[j][1]));
            asm("mov.b64 {%0,%1}, %2;" : "=f"(o[4]), "=f"(o[5]) : "l"(acc[j][2]));
            asm("mov.b64 {%0,%1}, %2;" : "=f"(o[6]), "=f"(o[7]) : "l"(acc[j][3]));
            uint2 u0, u1;
            u0.x = pack_h2(o[0] * di, o[1] * di);
            u0.y = pack_h2(o[2] * di, o[3] * di);
            u1.x = pack_h2(o[4] * di, o[5] * di);
            u1.y = pack_h2(o[6] * di, o[7] * di);
            __half2* hp = H16 + node * (HID / 2) + cA / 2;
            __half2* ap = AGG16 + node * (HID / 2) + cA / 2;
            *(uint2*)hp = u0;
            *(uint2*)(hp + 16) = u1;          // +32 cols
            *(uint2*)ap = u0;                 // self-loop init
            *(uint2*)(ap + 16) = u1;
        }
    }
}

// ---------------------------------------------------------------------------
// aggregation: agg[dst] += h'[src]; fp16 all the way.
// 8 lanes per edge; each lane: one uint4 gather (8 halves) + one v4.f16x2 RED.
__global__ void agg_kernel(const int* __restrict__ src, const int* __restrict__ dst,
                           const __half2* __restrict__ h16, __half2* __restrict__ agg, int e) {
    int tid = blockIdx.x * blockDim.x + threadIdx.x;
    int edge = tid >> 3;
    int q = tid & 7;
    if (edge >= e) return;
    int s = __ldg(src + edge);
    int d = __ldg(dst + edge);
    uint4 raw = __ldg((const uint4*)(h16 + s * (HID / 2) + q * 4));
    __half2* p = agg + d * (HID / 2) + q * 4;
    asm volatile("red.global.add.noftz.v4.f16x2 [%0], {%1,%2,%3,%4};"
                 :: "l"(p), "r"(raw.x), "r"(raw.y), "r"(raw.z), "r"(raw.w) : "memory");
}

// ---------------------------------------------------------------------------
// decode: out[e] = dot(z[src], z[dst]), z = rsqrt(deg)*agg2 + b2 inline.
// 8 lanes per edge; each lane gathers 8 halves (uint4) per endpoint.
__global__ void decode_kernel(const int* __restrict__ src, const int* __restrict__ dst,
                              const __half2* __restrict__ agg,
                              const float* __restrict__ b,
                              float* __restrict__ out, int e) {
    int tid = blockIdx.x * blockDim.x + threadIdx.x;
    int edge = tid >> 3;
    int q = tid & 7;
    if (edge >= e) return;
    int s = __ldg(src + edge);
    int d = __ldg(dst + edge);
    float ds = rsqrtf(g_deg[s]);
    float dd = rsqrtf(g_deg[d]);
    uint4 rs = __ldg((const uint4*)(agg + s * (HID / 2) + q * 4));
    uint4 rd = __ldg((const uint4*)(agg + d * (HID / 2) + q * 4));
    float4 b0 = *(const float4*)(b + q * 8);
    float4 b1 = *(const float4*)(b + q * 8 + 4);
    float p = 0.f;
    {
        float2 fs, fd;
        fs = __half22float2(*(__half2*)&rs.x); fd = __half22float2(*(__half2*)&rd.x);
        p = fmaf(fmaf(ds, fs.x, b0.x), fmaf(dd, fd.x, b0.x), p);
        p = fmaf(fmaf(ds, fs.y, b0.y), fmaf(dd, fd.y, b0.y), p);
        fs = __half22float2(*(__half2*)&rs.y); fd = __half22float2(*(__half2*)&rd.y);
        p = fmaf(fmaf(ds, fs.x, b0.z), fmaf(dd, fd.x, b0.z), p);
        p = fmaf(fmaf(ds, fs.y, b0.w), fmaf(dd, fd.y, b0.w), p);
        fs = __half22float2(*(__half2*)&rs.z); fd = __half22float2(*(__half2*)&rd.z);
        p = fmaf(fmaf(ds, fs.x, b1.x), fmaf(dd, fd.x, b1.x), p);
        p = fmaf(fmaf(ds, fs.y, b1.y), fmaf(dd, fd.y, b1.y), p);
        fs = __half22float2(*(__half2*)&rs.w); fd = __half22float2(*(__half2*)&rd.w);
        p = fmaf(fmaf(ds, fs.x, b1.z), fmaf(dd, fd.x, b1.z), p);
        p = fmaf(fmaf(ds, fs.y, b1.w), fmaf(dd, fd.y, b1.w), p);
    }
    p += __shfl_xor_sync(0xffffffffu, p, 4);
    p += __shfl_xor_sync(0xffffffffu, p, 2);
    p += __shfl_xor_sync(0xffffffffu, p, 1);
    if (q == 0) out[edge] = p;
}

// ---------------------------------------------------------------------------
extern "C" void kernel_launch(void* const* d_in, const int* in_sizes, int n_in,
                              void* d_out, int out_size) {
    const float* x  = (const float*)d_in[0];   // [n, IN_CH]
    const int*   ei = (const int*)d_in[1];     // [2, e]
    const float* W1 = (const float*)d_in[2];
    const float* b1 = (const float*)d_in[3];
    const float* W2 = (const float*)d_in[4];
    const float* b2 = (const float*)d_in[5];
    float* out = (float*)d_out;                // [e]

    int n = in_sizes[0] / IN_CH;
    int e = in_sizes[1] / 2;
    const int* src = ei;
    const int* dst = ei + e;

    __half2 *p_h16, *p_agg1, *p_agg2;
    cudaGetSymbolAddress((void**)&p_h16, g_h16);
    cudaGetSymbolAddress((void**)&p_agg1, g_agg1);
    cudaGetSymbolAddress((void**)&p_agg2, g_agg2);

    const int T = 256;
    int eg8 = (e * 8 + T - 1) / T;             // 8 lanes per edge

    init_deg_kernel<<<(n + T - 1) / T, T>>>(n);
    degree_kernel<<<(e + T - 1) / T, T>>>(dst, e);

    // layer 1: h' = (X@W1)*dinv; fp16 to H16 + AGG1 (self-loop init)
    gemm_kernel<IN_CH, false><<<(n + 63) / 64, 128>>>(x, nullptr, W1, nullptr,
                                                      p_h16, p_agg1, n);
    agg_kernel<<<eg8, T>>>(src, dst, p_h16, p_agg1, e);

    // layer 2: input z1 = relu(dinv*agg1 + b1) read from fp16 agg1
    gemm_kernel<HID, true><<<(n + 63) / 64, 128>>>(nullptr, p_agg1, W2, b1,
                                                   p_h16, p_agg2, n);
    agg_kernel<<<eg8, T>>>(src, dst, p_h16, p_agg2, e);

    // decode straight from fp16 agg2 (z2 = dinv*agg2 + b2 inline)
    decode_kernel<<<eg8, T>>>(src, dst, p_agg2, b2, out, e);
}

// round 16
// speedup vs baseline: 1.0168x; 1.0168x over previous
#include <cuda_runtime.h>
#include <cuda_fp16.h>
#include <math.h>

#define IN_CH 128
#define HID 64
#define NMAX 50000
#define EMAX 800000

// Scratch (__device__ globals; no allocation allowed)
__device__ float   g_deg[NMAX];               // degree (raw; consumers rsqrt)
__device__ __half2 g_h16[NMAX * (HID / 2)];   // h' fp16 (gather source, both layers)
__device__ __half2 g_agg1[NMAX * (HID / 2)];  // layer-1 aggregation (fp16 REDs)
__device__ __half2 g_agg2[NMAX * (HID / 2)];  // layer-2 aggregation (fp16 REDs)

// pack two fp32 into one 32-bit half2 payload
static __device__ __forceinline__ unsigned pack_h2(float a, float b) {
    __half2 h = __floats2half2_rn(a, b);
    return *(unsigned*)&h;
}

// ---------------------------------------------------------------------------
__global__ void init_deg_kernel(int n) {
    int i = blockIdx.x * blockDim.x + threadIdx.x;
    if (i < n) g_deg[i] = 1.0f;               // self-loop contributes 1
}

__global__ void degree_kernel(const int* __restrict__ dst, int e) {
    int i = blockIdx.x * blockDim.x + threadIdx.x;
    if (i < e) {
        float* p = &g_deg[__ldg(dst + i)];
        asm volatile("red.global.add.f32 [%0], %1;" :: "l"(p), "f"(1.0f) : "memory");
    }
}

// ---------------------------------------------------------------------------
// GEMM: out[i][c] = dinv[i] * sum_k in[i][k] * W[k][c],  dinv = rsqrt(deg) inline.
// Dual-store fp16: -> H16 (edge gather source) and -> AGG16 (self-loop init).
// TRANS: input read from fp16 AGG of previous layer, z = relu(dinv*agg + bIn).
// 256 threads -> 128 nodes x 64 cols (grid 391, ~21 warps/SM).
// Thread (tx,ty): cols {4tx..+4, 4tx+32..+4}, nodes 4*ty..+4.
// Per warp-k: 2 W LDS.128 + 1 X LDS.128 feed 16 FFMA2 -> fma-bound with cover.
template <int K, bool TRANS>
__global__ void __launch_bounds__(256, 3)
gemm_kernel(const float* __restrict__ X, const __half2* __restrict__ X16,
            const float* __restrict__ W, const float* __restrict__ bIn,
            __half2* __restrict__ H16, __half2* __restrict__ AGG16, int n) {
    constexpr int KC = 64;
    constexpr int NC = K / KC;
    __shared__ float Ws[KC * HID];            // 16KB [k][col]
    __shared__ float Xs[KC * 128];            // 32KB [k][node] (transposed)
    const int t = threadIdx.x;
    const int node0 = blockIdx.x * 128;

    // X-fill role: 2 threads per row, each half of the k-chunk
    const int xr = t >> 1;                    // row 0..127
    const int xq = (t & 1) * 32;              // k-offset within chunk (0 or 32)
    const int xnode = node0 + xr;
    const bool xok = xnode < n;
    const float xdi = (TRANS && xok) ? rsqrtf(g_deg[xnode]) : 0.f;

    const int tx = t & 7;
    const int ty = t >> 3;                    // 0..31
    const int cA = tx * 4;
    const int n0 = ty * 4;                    // 4 nodes per thread

    unsigned long long acc[4][4];             // [node j][col pair] f32x2
#pragma unroll
    for (int j = 0; j < 4; ++j)
#pragma unroll
        for (int p = 0; p < 4; ++p) acc[j][p] = 0ULL;

#pragma unroll
    for (int c = 0; c < NC; ++c) {
        const int k0 = c * KC;
        if (c) __syncthreads();

        // W chunk: 4096 floats / 256 threads = 4 float4 each, coalesced
#pragma unroll
        for (int i = 0; i < KC * HID / 1024; ++i)
            *(float4*)(Ws + i * 1024 + t * 4) =
                *(const float4*)(W + k0 * HID + i * 1024 + t * 4);

        // X chunk: 2 threads per row, transpose into Xs[k][node]
#pragma unroll
        for (int g = 0; g < 8; ++g) {
            int koff = xq + g * 4;            // within-chunk k of this float4
            float4 v = make_float4(0.f, 0.f, 0.f, 0.f);
            if (xok) {
                if (TRANS) {
                    uint2 r = *(const uint2*)(X16 + xnode * (HID / 2) + (k0 + koff) / 2);
                    float2 f0 = __half22float2(*(__half2*)&r.x);
                    float2 f1 = __half22float2(*(__half2*)&r.y);
                    float4 bb = *(const float4*)(bIn + k0 + koff);
                    v.x = fmaxf(fmaf(xdi, f0.x, bb.x), 0.f);
                    v.y = fmaxf(fmaf(xdi, f0.y, bb.y), 0.f);
                    v.z = fmaxf(fmaf(xdi, f1.x, bb.z), 0.f);
                    v.w = fmaxf(fmaf(xdi, f1.y, bb.w), 0.f);
                } else {
                    v = *(const float4*)(X + xnode * K + k0 + koff);
                }
            }
            Xs[(koff + 0) * 128 + xr] = v.x;
            Xs[(koff + 1) * 128 + xr] = v.y;
            Xs[(koff + 2) * 128 + xr] = v.z;
            Xs[(koff + 3) * 128 + xr] = v.w;
        }
        __syncthreads();

#pragma unroll 4
        for (int k = 0; k < KC; ++k) {
            ulonglong2 wA = *(const ulonglong2*)(Ws + k * HID + cA);
            ulonglong2 wB = *(const ulonglong2*)(Ws + k * HID + cA + 32);
            float4 xa = *(const float4*)(Xs + k * 128 + n0);
            float xs[4] = {xa.x, xa.y, xa.z, xa.w};
#pragma unroll
            for (int j = 0; j < 4; ++j) {
                unsigned long long xx;
                asm("mov.b64 %0, {%1, %1};" : "=l"(xx) : "f"(xs[j]));
                asm("fma.rn.f32x2 %0, %1, %2, %0;" : "+l"(acc[j][0]) : "l"(wA.x), "l"(xx));
                asm("fma.rn.f32x2 %0, %1, %2, %0;" : "+l"(acc[j][1]) : "l"(wA.y), "l"(xx));
                asm("fma.rn.f32x2 %0, %1, %2, %0;" : "+l"(acc[j][2]) : "l"(wB.x), "l"(xx));
                asm("fma.rn.f32x2 %0, %1, %2, %0;" : "+l"(acc[j][3]) : "l"(wB.y), "l"(xx));
            }
        }
    }

#pragma unroll
    for (int j = 0; j < 4; ++j) {
        int node = node0 + n0 + j;
        if (node < n) {
            float di = rsqrtf(g_deg[node]);
            float o[8];
            asm("mov.b64 {%0,%1}, %2;" : "=f"(o[0]), "=f"(o[1]) : "l"(acc[j][0]));
            asm("mov.b64 {%0,%1}, %2;" : "=f"(o[2]), "=f"(o[3]) : "l"(acc[j][1]));
            asm("mov.b64 {%0,%1}, %2;" : "=f"(o[4]), "=f"(o[5]) : "l"(acc[j][2]));
            asm("mov.b64 {%0,%1}, %2;" : "=f"(o[6]), "=f"(o[7]) : "l"(acc[j][3]));
            uint2 u0, u1;
            u0.x = pack_h2(o[0] * di, o[1] * di);
            u0.y = pack_h2(o[2] * di, o[3] * di);
            u1.x = pack_h2(o[4] * di, o[5] * di);
            u1.y = pack_h2(o[6] * di, o[7] * di);
            __half2* hp = H16 + node * (HID / 2) + cA / 2;
            __half2* ap = AGG16 + node * (HID / 2) + cA / 2;
            *(uint2*)hp = u0;
            *(uint2*)(hp + 16) = u1;          // +32 cols
            *(uint2*)ap = u0;                 // self-loop init
            *(uint2*)(ap + 16) = u1;
        }
    }
}

// ---------------------------------------------------------------------------
// aggregation: agg[dst] += h'[src]; fp16 all the way.
// 8 lanes per edge; each lane: one uint4 gather (8 halves) + one v4.f16x2 RED.
__global__ void agg_kernel(const int* __restrict__ src, const int* __restrict__ dst,
                           const __half2* __restrict__ h16, __half2* __restrict__ agg, int e) {
    int tid = blockIdx.x * blockDim.x + threadIdx.x;
    int edge = tid >> 3;
    int q = tid & 7;
    if (edge >= e) return;
    int s = __ldg(src + edge);
    int d = __ldg(dst + edge);
    uint4 raw = __ldg((const uint4*)(h16 + s * (HID / 2) + q * 4));
    __half2* p = agg + d * (HID / 2) + q * 4;
    asm volatile("red.global.add.noftz.v4.f16x2 [%0], {%1,%2,%3,%4};"
                 :: "l"(p), "r"(raw.x), "r"(raw.y), "r"(raw.z), "r"(raw.w) : "memory");
}

// ---------------------------------------------------------------------------
// decode: out[e] = dot(z[src], z[dst]), z = rsqrt(deg)*agg2 + b2 inline.
// 8 lanes per edge; each lane gathers 8 halves (uint4) per endpoint.
__global__ void decode_kernel(const int* __restrict__ src, const int* __restrict__ dst,
                              const __half2* __restrict__ agg,
                              const float* __restrict__ b,
                              float* __restrict__ out, int e) {
    int tid = blockIdx.x * blockDim.x + threadIdx.x;
    int edge = tid >> 3;
    int q = tid & 7;
    if (edge >= e) return;
    int s = __ldg(src + edge);
    int d = __ldg(dst + edge);
    float ds = rsqrtf(g_deg[s]);
    float dd = rsqrtf(g_deg[d]);
    uint4 rs = __ldg((const uint4*)(agg + s * (HID / 2) + q * 4));
    uint4 rd = __ldg((const uint4*)(agg + d * (HID / 2) + q * 4));
    float4 b0 = *(const float4*)(b + q * 8);
    float4 b1 = *(const float4*)(b + q * 8 + 4);
    float p = 0.f;
    {
        float2 fs, fd;
        fs = __half22float2(*(__half2*)&rs.x); fd = __half22float2(*(__half2*)&rd.x);
        p = fmaf(fmaf(ds, fs.x, b0.x), fmaf(dd, fd.x, b0.x), p);
        p = fmaf(fmaf(ds, fs.y, b0.y), fmaf(dd, fd.y, b0.y), p);
        fs = __half22float2(*(__half2*)&rs.y); fd = __half22float2(*(__half2*)&rd.y);
        p = fmaf(fmaf(ds, fs.x, b0.z), fmaf(dd, fd.x, b0.z), p);
        p = fmaf(fmaf(ds, fs.y, b0.w), fmaf(dd, fd.y, b0.w), p);
        fs = __half22float2(*(__half2*)&rs.z); fd = __half22float2(*(__half2*)&rd.z);
        p = fmaf(fmaf(ds, fs.x, b1.x), fmaf(dd, fd.x, b1.x), p);
        p = fmaf(fmaf(ds, fs.y, b1.y), fmaf(dd, fd.y, b1.y), p);
        fs = __half22float2(*(__half2*)&rs.w); fd = __half22float2(*(__half2*)&rd.w);
        p = fmaf(fmaf(ds, fs.x, b1.z), fmaf(dd, fd.x, b1.z), p);
        p = fmaf(fmaf(ds, fs.y, b1.w), fmaf(dd, fd.y, b1.w), p);
    }
    p += __shfl_xor_sync(0xffffffffu, p, 4);
    p += __shfl_xor_sync(0xffffffffu, p, 2);
    p += __shfl_xor_sync(0xffffffffu, p, 1);
    if (q == 0) out[edge] = p;
}

// ---------------------------------------------------------------------------
extern "C" void kernel_launch(void* const* d_in, const int* in_sizes, int n_in,
                              void* d_out, int out_size) {
    const float* x  = (const float*)d_in[0];   // [n, IN_CH]
    const int*   ei = (const int*)d_in[1];     // [2, e]
    const float* W1 = (const float*)d_in[2];
    const float* b1 = (const float*)d_in[3];
    const float* W2 = (const float*)d_in[4];
    const float* b2 = (const float*)d_in[5];
    float* out = (float*)d_out;                // [e]

    int n = in_sizes[0] / IN_CH;
    int e = in_sizes[1] / 2;
    const int* src = ei;
    const int* dst = ei + e;

    __half2 *p_h16, *p_agg1, *p_agg2;
    cudaGetSymbolAddress((void**)&p_h16, g_h16);
    cudaGetSymbolAddress((void**)&p_agg1, g_agg1);
    cudaGetSymbolAddress((void**)&p_agg2, g_agg2);

    const int T = 256;
    int eg8 = (e * 8 + T - 1) / T;             // 8 lanes per edge

    init_deg_kernel<<<(n + T - 1) / T, T>>>(n);
    degree_kernel<<<(e + T - 1) / T, T>>>(dst, e);

    // layer 1: h' = (X@W1)*dinv; fp16 to H16 + AGG1 (self-loop init)
    gemm_kernel<IN_CH, false><<<(n + 127) / 128, T>>>(x, nullptr, W1, nullptr,
                                                      p_h16, p_agg1, n);
    agg_kernel<<<eg8, T>>>(src, dst, p_h16, p_agg1, e);

    // layer 2: input z1 = relu(dinv*agg1 + b1) read from fp16 agg1
    gemm_kernel<HID, true><<<(n + 127) / 128, T>>>(nullptr, p_agg1, W2, b1,
                                                   p_h16, p_agg2, n);
    agg_kernel<<<eg8, T>>>(src, dst, p_h16, p_agg2, e);

    // decode straight from fp16 agg2 (z2 = dinv*agg2 + b2 inline)
    decode_kernel<<<eg8, T>>>(src, dst, p_agg2, b2, out, e);
}

// round 17
// speedup vs baseline: 1.0368x; 1.0196x over previous
#include <cuda_runtime.h>
#include <cuda_fp16.h>
#include <math.h>

#define IN_CH 128
#define HID 64
#define NMAX 50000
#define EMAX 800000

// Scratch (__device__ globals; no allocation allowed)
__device__ float   g_deg[NMAX];               // degree (raw; consumers rsqrt)
__device__ __half2 g_h16[NMAX * (HID / 2)];   // h' fp16 (gather source, both layers)
__device__ __half2 g_agg1[NMAX * (HID / 2)];  // layer-1 aggregation (fp16 REDs)
__device__ __half2 g_agg2[NMAX * (HID / 2)];  // layer-2 aggregation (fp16 REDs)

// pack two fp32 into one 32-bit half2 payload
static __device__ __forceinline__ unsigned pack_h2(float a, float b) {
    __half2 h = __floats2half2_rn(a, b);
    return *(unsigned*)&h;
}

// ---------------------------------------------------------------------------
__global__ void init_deg_kernel(int n) {
    int i = blockIdx.x * blockDim.x + threadIdx.x;
    if (i < n) g_deg[i] = 1.0f;               // self-loop contributes 1
}

__global__ void degree_kernel(const int* __restrict__ dst, int e) {
    int i = blockIdx.x * blockDim.x + threadIdx.x;
    if (i < e) {
        float* p = &g_deg[__ldg(dst + i)];
        asm volatile("red.global.add.f32 [%0], %1;" :: "l"(p), "f"(1.0f) : "memory");
    }
}

// ---------------------------------------------------------------------------
// GEMM: out[i][c] = dinv[i] * sum_k in[i][k] * W[k][c],  dinv = rsqrt(deg) inline.
// Dual-store fp16: -> H16 (edge gather source) and -> AGG16 (self-loop init).
// TRANS: input read from fp16 AGG of previous layer, z = relu(dinv*agg + bIn).
// 128 threads -> 128 nodes x 64 cols; K in chunks of 64 (R10/R14-proven shape).
// Latency strategy: grid caps occupancy at ~2.6 CTA/SM, so no reg clamp —
// ptxas gets headroom to software-pipeline the unroll-8 K loop (batched LDS).
template <int K, bool TRANS>
__global__ void __launch_bounds__(128)
gemm_kernel(const float* __restrict__ X, const __half2* __restrict__ X16,
            const float* __restrict__ W, const float* __restrict__ bIn,
            __half2* __restrict__ H16, __half2* __restrict__ AGG16, int n) {
    constexpr int KC = 64;
    constexpr int NC = K / KC;
    __shared__ float Ws[KC * HID];            // 16KB [k][col]
    __shared__ float Xs[KC * 128];            // 32KB [k][node] (transposed)
    const int t = threadIdx.x;
    const int node0 = blockIdx.x * 128;
    const int mynode = node0 + t;
    const bool ok = mynode < n;
    const float mydi = (TRANS && ok) ? rsqrtf(g_deg[mynode]) : 0.f;

    const int tx = t & 7;
    const int ty = t >> 3;                    // 0..15
    const int cA = tx * 4;
    const int n0 = ty * 8;

    unsigned long long acc[8][4];
#pragma unroll
    for (int j = 0; j < 8; ++j)
#pragma unroll
        for (int p = 0; p < 4; ++p) acc[j][p] = 0ULL;

#pragma unroll
    for (int c = 0; c < NC; ++c) {
        const int k0 = c * KC;
        if (c) __syncthreads();

#pragma unroll
        for (int i = 0; i < KC * HID / 512; ++i)
            *(float4*)(Ws + i * 512 + t * 4) =
                *(const float4*)(W + k0 * HID + i * 512 + t * 4);

#pragma unroll
        for (int g = 0; g < KC / 4; ++g) {
            float4 v = make_float4(0.f, 0.f, 0.f, 0.f);
            if (ok) {
                if (TRANS) {
                    uint2 r = *(const uint2*)(X16 + mynode * (HID / 2) + (k0 + g * 4) / 2);
                    float2 f0 = __half22float2(*(__half2*)&r.x);
                    float2 f1 = __half22float2(*(__half2*)&r.y);
                    float4 bb = *(const float4*)(bIn + k0 + g * 4);
                    v.x = fmaxf(fmaf(mydi, f0.x, bb.x), 0.f);
                    v.y = fmaxf(fmaf(mydi, f0.y, bb.y), 0.f);
                    v.z = fmaxf(fmaf(mydi, f1.x, bb.z), 0.f);
                    v.w = fmaxf(fmaf(mydi, f1.y, bb.w), 0.f);
                } else {
                    v = *(const float4*)(X + mynode * K + k0 + g * 4);
                }
            }
            Xs[(g * 4 + 0) * 128 + t] = v.x;
            Xs[(g * 4 + 1) * 128 + t] = v.y;
            Xs[(g * 4 + 2) * 128 + t] = v.z;
            Xs[(g * 4 + 3) * 128 + t] = v.w;
        }
        __syncthreads();

#pragma unroll 8
        for (int k = 0; k < KC; ++k) {
            ulonglong2 wA = *(const ulonglong2*)(Ws + k * HID + cA);
            ulonglong2 wB = *(const ulonglong2*)(Ws + k * HID + cA + 32);
            float4 xa = *(const float4*)(Xs + k * 128 + n0);
            float4 xb = *(const float4*)(Xs + k * 128 + n0 + 4);
            float xs[8] = {xa.x, xa.y, xa.z, xa.w, xb.x, xb.y, xb.z, xb.w};
#pragma unroll
            for (int j = 0; j < 8; ++j) {
                unsigned long long xx;
                asm("mov.b64 %0, {%1, %1};" : "=l"(xx) : "f"(xs[j]));
                asm("fma.rn.f32x2 %0, %1, %2, %0;" : "+l"(acc[j][0]) : "l"(wA.x), "l"(xx));
                asm("fma.rn.f32x2 %0, %1, %2, %0;" : "+l"(acc[j][1]) : "l"(wA.y), "l"(xx));
                asm("fma.rn.f32x2 %0, %1, %2, %0;" : "+l"(acc[j][2]) : "l"(wB.x), "l"(xx));
                asm("fma.rn.f32x2 %0, %1, %2, %0;" : "+l"(acc[j][3]) : "l"(wB.y), "l"(xx));
            }
        }
    }

#pragma unroll
    for (int j = 0; j < 8; ++j) {
        int node = node0 + n0 + j;
        if (node < n) {
            float di = rsqrtf(g_deg[node]);
            float o[8];
            asm("mov.b64 {%0,%1}, %2;" : "=f"(o[0]), "=f"(o[1]) : "l"(acc[j][0]));
            asm("mov.b64 {%0,%1}, %2;" : "=f"(o[2]), "=f"(o[3]) : "l"(acc[j][1]));
            asm("mov.b64 {%0,%1}, %2;" : "=f"(o[4]), "=f"(o[5]) : "l"(acc[j][2]));
            asm("mov.b64 {%0,%1}, %2;" : "=f"(o[6]), "=f"(o[7]) : "l"(acc[j][3]));
            uint2 u0, u1;
            u0.x = pack_h2(o[0] * di, o[1] * di);
            u0.y = pack_h2(o[2] * di, o[3] * di);
            u1.x = pack_h2(o[4] * di, o[5] * di);
            u1.y = pack_h2(o[6] * di, o[7] * di);
            __half2* hp = H16 + node * (HID / 2) + cA / 2;
            __half2* ap = AGG16 + node * (HID / 2) + cA / 2;
            *(uint2*)hp = u0;
            *(uint2*)(hp + 16) = u1;          // +32 cols
            *(uint2*)ap = u0;                 // self-loop init
            *(uint2*)(ap + 16) = u1;
        }
    }
}

// ---------------------------------------------------------------------------
// aggregation: agg[dst] += h'[src]; fp16 all the way.
// 8 lanes per edge; each lane: one uint4 gather (8 halves) + one v4.f16x2 RED.
__global__ void agg_kernel(const int* __restrict__ src, const int* __restrict__ dst,
                           const __half2* __restrict__ h16, __half2* __restrict__ agg, int e) {
    int tid = blockIdx.x * blockDim.x + threadIdx.x;
    int edge = tid >> 3;
    int q = tid & 7;
    if (edge >= e) return;
    int s = __ldg(src + edge);
    int d = __ldg(dst + edge);
    uint4 raw = __ldg((const uint4*)(h16 + s * (HID / 2) + q * 4));
    __half2* p = agg + d * (HID / 2) + q * 4;
    asm volatile("red.global.add.noftz.v4.f16x2 [%0], {%1,%2,%3,%4};"
                 :: "l"(p), "r"(raw.x), "r"(raw.y), "r"(raw.z), "r"(raw.w) : "memory");
}

// ---------------------------------------------------------------------------
// decode: out[e] = dot(z[src], z[dst]), z = rsqrt(deg)*agg2 + b2 inline.
// 8 lanes per edge; each lane gathers 8 halves (uint4) per endpoint.
__global__ void decode_kernel(const int* __restrict__ src, const int* __restrict__ dst,
                              const __half2* __restrict__ agg,
                              const float* __restrict__ b,
                              float* __restrict__ out, int e) {
    int tid = blockIdx.x * blockDim.x + threadIdx.x;
    int edge = tid >> 3;
    int q = tid & 7;
    if (edge >= e) return;
    int s = __ldg(src + edge);
    int d = __ldg(dst + edge);
    float ds = rsqrtf(g_deg[s]);
    float dd = rsqrtf(g_deg[d]);
    uint4 rs = __ldg((const uint4*)(agg + s * (HID / 2) + q * 4));
    uint4 rd = __ldg((const uint4*)(agg + d * (HID / 2) + q * 4));
    float4 b0 = *(const float4*)(b + q * 8);
    float4 b1 = *(const float4*)(b + q * 8 + 4);
    float p = 0.f;
    {
        float2 fs, fd;
        fs = __half22float2(*(__half2*)&rs.x); fd = __half22float2(*(__half2*)&rd.x);
        p = fmaf(fmaf(ds, fs.x, b0.x), fmaf(dd, fd.x, b0.x), p);
        p = fmaf(fmaf(ds, fs.y, b0.y), fmaf(dd, fd.y, b0.y), p);
        fs = __half22float2(*(__half2*)&rs.y); fd = __half22float2(*(__half2*)&rd.y);
        p = fmaf(fmaf(ds, fs.x, b0.z), fmaf(dd, fd.x, b0.z), p);
        p = fmaf(fmaf(ds, fs.y, b0.w), fmaf(dd, fd.y, b0.w), p);
        fs = __half22float2(*(__half2*)&rs.z); fd = __half22float2(*(__half2*)&rd.z);
        p = fmaf(fmaf(ds, fs.x, b1.x), fmaf(dd, fd.x, b1.x), p);
        p = fmaf(fmaf(ds, fs.y, b1.y), fmaf(dd, fd.y, b1.y), p);
        fs = __half22float2(*(__half2*)&rs.w); fd = __half22float2(*(__half2*)&rd.w);
        p = fmaf(fmaf(ds, fs.x, b1.z), fmaf(dd, fd.x, b1.z), p);
        p = fmaf(fmaf(ds, fs.y, b1.w), fmaf(dd, fd.y, b1.w), p);
    }
    p += __shfl_xor_sync(0xffffffffu, p, 4);
    p += __shfl_xor_sync(0xffffffffu, p, 2);
    p += __shfl_xor_sync(0xffffffffu, p, 1);
    if (q == 0) out[edge] = p;
}

// ---------------------------------------------------------------------------
extern "C" void kernel_launch(void* const* d_in, const int* in_sizes, int n_in,
                              void* d_out, int out_size) {
    const float* x  = (const float*)d_in[0];   // [n, IN_CH]
    const int*   ei = (const int*)d_in[1];     // [2, e]
    const float* W1 = (const float*)d_in[2];
    const float* b1 = (const float*)d_in[3];
    const float* W2 = (const float*)d_in[4];
    const float* b2 = (const float*)d_in[5];
    float* out = (float*)d_out;                // [e]

    int n = in_sizes[0] / IN_CH;
    int e = in_sizes[1] / 2;
    const int* src = ei;
    const int* dst = ei + e;

    __half2 *p_h16, *p_agg1, *p_agg2;
    cudaGetSymbolAddress((void**)&p_h16, g_h16);
    cudaGetSymbolAddress((void**)&p_agg1, g_agg1);
    cudaGetSymbolAddress((void**)&p_agg2, g_agg2);

    const int T = 256;
    int eg8 = (e * 8 + T - 1) / T;             // 8 lanes per edge

    init_deg_kernel<<<(n + T - 1) / T, T>>>(n);
    degree_kernel<<<(e + T - 1) / T, T>>>(dst, e);

    // layer 1: h' = (X@W1)*dinv; fp16 to H16 + AGG1 (self-loop init)
    gemm_kernel<IN_CH, false><<<(n + 127) / 128, 128>>>(x, nullptr, W1, nullptr,
                                                        p_h16, p_agg1, n);
    agg_kernel<<<eg8, T>>>(src, dst, p_h16, p_agg1, e);

    // layer 2: input z1 = relu(dinv*agg1 + b1) read from fp16 agg1
    gemm_kernel<HID, true><<<(n + 127) / 128, 128>>>(nullptr, p_agg1, W2, b1,
                                                     p_h16, p_agg2, n);
    agg_kernel<<<eg8, T>>>(src, dst, p_h16, p_agg2, e);

    // decode straight from fp16 agg2 (z2 = dinv*agg2 + b2 inline)
    decode_kernel<<<eg8, T>>>(src, dst, p_agg2, b2, out, e);
}